// round 15
// baseline (speedup 1.0000x reference)
#include <cuda_runtime.h>
#include <math.h>
#include <stdint.h>

// Problem constants
#define B_    4
#define T_    2048
#define DM_   2048
#define H_    16
#define HKV_  4
#define D_    128
#define M_    (B_*T_)      // 8192 tokens
#define NQ_   (H_*D_)      // 2048
#define NKV_  (HKV_*D_)    // 512

#define NSM_SLOTS 296      // 148 SMs x 2 CTAs (persistent Wo GEMM grid)

// Scratch (device globals: allocation-free per harness rules)
__device__ float g_q  [M_*NQ_];
__device__ float g_k  [M_*NKV_];
__device__ float g_v  [M_*NKV_];
__device__ float g_att[M_*NQ_];
__device__ float g_wq [NQ_*DM_];
__device__ float g_wk [NKV_*DM_];
__device__ float g_wv [NKV_*DM_];
__device__ float g_wo [DM_*NQ_];
__device__ float g_rope[T_*64*2];

// ---------------------------------------------------------------------------
// Helpers
// ---------------------------------------------------------------------------
__device__ __forceinline__ uint32_t smem_u32(const void* p) {
    uint32_t a;
    asm("{ .reg .u64 t; cvta.to.shared.u64 t, %1; cvt.u32.u64 %0, t; }" : "=r"(a) : "l"(p));
    return a;
}
__device__ __forceinline__ float rna_tf32(float v) {
    uint32_t b;
    asm("cvt.rna.tf32.f32 %0, %1;" : "=r"(b) : "f"(v));
    return __uint_as_float(b);
}
__device__ __forceinline__ uint32_t rna_tf32_u(float v) {
    uint32_t b;
    asm("cvt.rna.tf32.f32 %0, %1;" : "=r"(b) : "f"(v));
    return b;
}

#define CP_ASYNC16(dst, src) \
    asm volatile("cp.async.cg.shared.global [%0], [%1], 16;" :: "r"(dst), "l"(src) : "memory")
#define CP_COMMIT()  asm volatile("cp.async.commit_group;" ::: "memory")
#define CP_WAIT(n)   asm volatile("cp.async.wait_group %0;" :: "n"(n) : "memory")

// mma.sync m16n8k8 tf32 (family-portable)
#define MMA_TF32(c, a, b) \
    asm volatile("mma.sync.aligned.m16n8k8.row.col.f32.tf32.tf32.f32 " \
        "{%0,%1,%2,%3}, {%4,%5,%6,%7}, {%8,%9}, {%0,%1,%2,%3};" \
        : "+f"((c)[0]), "+f"((c)[1]), "+f"((c)[2]), "+f"((c)[3]) \
        : "r"((a)[0]), "r"((a)[1]), "r"((a)[2]), "r"((a)[3]), \
          "r"((b)[0]), "r"((b)[1]))

// ---------------------------------------------------------------------------
// Prepass: RNA-round W matrices + RoPE table, single launch.
// x is NOT pre-rounded anymore — the qkv GEMM rounds A-fragments in-register
// (bit-identical results, saves 128 MB of HBM traffic).
// ---------------------------------------------------------------------------
__global__ void prepass_all_kernel(
    const float* __restrict__ Wq, const float* __restrict__ Wk,
    const float* __restrict__ Wv, const float* __restrict__ Wo,
    float* __restrict__ owq, float* __restrict__ owk,
    float* __restrict__ owv, float* __restrict__ owo, float* __restrict__ rope)
{
    const long n_q  = (long)NQ_ * DM_ / 4;
    const long n_kv = (long)NKV_* DM_ / 4;
    const long n_f4 = 2*n_q + 2*n_kv;
    long j = blockIdx.x * (long)blockDim.x + threadIdx.x;

    if (j < n_f4) {
        const float* src; float* dst; long i = j;
        if (i < n_q)                 { src = Wq; dst = owq; }
        else if ((i -= n_q) < n_kv)  { src = Wk; dst = owk; }
        else if ((i -= n_kv) < n_kv) { src = Wv; dst = owv; }
        else                         { i -= n_kv; src = Wo; dst = owo; }
        float4 v = ((const float4*)src)[i];
        v.x = rna_tf32(v.x); v.y = rna_tf32(v.y); v.z = rna_tf32(v.z); v.w = rna_tf32(v.w);
        ((float4*)dst)[i] = v;
        return;
    }
    long r = j - n_f4;
    if (r < (long)T_ * 64) {
        int t = (int)(r >> 6), f = (int)(r & 63);
        double invf = exp(-((double)f / 64.0) * log(10000.0));
        float ang = (float)t * (float)invf;
        rope[r*2 + 0] = (float)cos((double)ang);
        rope[r*2 + 1] = (float)sin((double)ang);
    }
}

// ---------------------------------------------------------------------------
// GEMM core: CTA 128x128x32, 4 warps (64x64 warp tiles), 2 CTAs/SM.
// Proven 2-stage stride-40 mainloop. CVT_A: apply rna_tf32 to A-fragments at
// register-extract time (for raw-fp32 A; hides in idle issue slots).
// ---------------------------------------------------------------------------
#define STAGE_F 10240
#define STAGE_B (STAGE_F*4)

struct GemmCore {
    const float* Ab;
    const float* Wb;
    float* smf;
    uint32_t sbase;
    int tid, warp_m, warp_n, g, q4;

    __device__ __forceinline__ void load_stage(int s, int kt, int K) const {
        uint32_t aS = sbase + s * STAGE_B;
        uint32_t bS = aS + 20480;
        const float* ap = Ab + kt * 32;
        const float* wp = Wb + kt * 32;
        #pragma unroll
        for (int it = 0; it < 8; ++it) {
            int idx = it * 128 + tid;
            int row = idx >> 3, seg = idx & 7;
            uint32_t so = (uint32_t)row * 160 + (uint32_t)seg * 16;
            CP_ASYNC16(aS + so, ap + (size_t)row * K + seg * 4);
            CP_ASYNC16(bS + so, wp + (size_t)row * K + seg * 4);
        }
    }

    template<bool CVT_A>
    __device__ __forceinline__ void load_frags(const float* As_, const float* Bs_,
                                               int ks, uint32_t* a, uint32_t* b) const {
        const int col = ks * 8 + 2 * q4;
        #pragma unroll
        for (int ni = 0; ni < 8; ++ni) {
            float2 t = *(const float2*)&Bs_[(ni * 8 + g) * 40 + col];
            b[ni*2]   = __float_as_uint(t.x);
            b[ni*2+1] = __float_as_uint(t.y);
        }
        #pragma unroll
        for (int mi = 0; mi < 4; ++mi) {
            float2 t0 = *(const float2*)&As_[(mi * 16 + g) * 40 + col];
            float2 t1 = *(const float2*)&As_[(mi * 16 + g + 8) * 40 + col];
            if (CVT_A) {
                a[mi*4+0] = rna_tf32_u(t0.x);
                a[mi*4+2] = rna_tf32_u(t0.y);
                a[mi*4+1] = rna_tf32_u(t1.x);
                a[mi*4+3] = rna_tf32_u(t1.y);
            } else {
                a[mi*4+0] = __float_as_uint(t0.x);
                a[mi*4+2] = __float_as_uint(t0.y);
                a[mi*4+1] = __float_as_uint(t1.x);
                a[mi*4+3] = __float_as_uint(t1.y);
            }
        }
    }

    template<bool CVT_A>
    __device__ __forceinline__ void mainloop(float acc[4][8][4], int K) const {
        const int KT = K >> 5;
        load_stage(0, 0, K);
        CP_COMMIT();
        for (int kt = 0; kt < KT; ++kt) {
            const int cur = kt & 1;
            CP_WAIT(0);
            __syncthreads();
            if (kt + 1 < KT) {
                load_stage(cur ^ 1, kt + 1, K);
                CP_COMMIT();
            }
            const float* As_ = smf + cur * STAGE_F + warp_m * (64 * 40);
            const float* Bs_ = smf + cur * STAGE_F + 5120 + warp_n * (64 * 40);

            uint32_t aF[2][16], bF[2][16];
            load_frags<CVT_A>(As_, Bs_, 0, aF[0], bF[0]);
            #pragma unroll
            for (int ks = 0; ks < 4; ++ks) {
                const int cb = ks & 1;
                if (ks < 3) load_frags<CVT_A>(As_, Bs_, ks + 1, aF[cb ^ 1], bF[cb ^ 1]);
                #pragma unroll
                for (int mi = 0; mi < 4; ++mi)
                    #pragma unroll
                    for (int ni = 0; ni < 8; ++ni)
                        MMA_TF32(acc[mi][ni], &aF[cb][mi*4], &bF[cb][ni*2]);
            }
        }
        __syncthreads();   // all reads done; stage smem reusable
    }

    __device__ __forceinline__ void epilogue_plain(float acc[4][8][4], float* C,
                                                   int N, int row0, int col0, bool rnd) const {
        #pragma unroll
        for (int mi = 0; mi < 4; ++mi) {
            const int r = row0 + warp_m * 64 + mi * 16 + g;
            #pragma unroll
            for (int ni = 0; ni < 8; ++ni) {
                const int c = col0 + warp_n * 64 + ni * 8 + q4 * 2;
                float e0 = acc[mi][ni][0], e1 = acc[mi][ni][1];
                float e2 = acc[mi][ni][2], e3 = acc[mi][ni][3];
                if (rnd) { e0 = rna_tf32(e0); e1 = rna_tf32(e1); e2 = rna_tf32(e2); e3 = rna_tf32(e3); }
                *(float2*)&C[(size_t)r * N + c]       = make_float2(e0, e1);
                *(float2*)&C[(size_t)(r + 8) * N + c] = make_float2(e2, e3);
            }
        }
    }

    __device__ __forceinline__ void epilogue_fuse(float acc[4][8][4], float* C,
                                                  int N, int row0, int col0,
                                                  const float* rope, bool rnd) const {
        float* Cs = smf;   // 128*129 floats = 66048 B <= 2*STAGE_B (stages idle)
        #pragma unroll
        for (int mi = 0; mi < 4; ++mi) {
            const int r = warp_m * 64 + mi * 16 + g;
            #pragma unroll
            for (int ni = 0; ni < 8; ++ni) {
                const int c = warp_n * 64 + ni * 8 + q4 * 2;
                Cs[r * 129 + c]           = acc[mi][ni][0];
                Cs[r * 129 + c + 1]       = acc[mi][ni][1];
                Cs[(r + 8) * 129 + c]     = acc[mi][ni][2];
                Cs[(r + 8) * 129 + c + 1] = acc[mi][ni][3];
            }
        }
        __syncthreads();
        {
            const int row = row0 + tid;          // 128 threads = 128 rows
            const float* cr = Cs + tid * 129;
            float ss = 0.f;
            #pragma unroll 16
            for (int j = 0; j < 128; ++j) ss += cr[j] * cr[j];
            const float sc = rsqrtf(ss * (1.0f/128.0f) + 1.1920928955078125e-07f);
            const float* rp = rope + (row & (T_ - 1)) * 128;
            float* op = C + (size_t)row * N + col0;
            #pragma unroll
            for (int f4 = 0; f4 < 64; f4 += 4) {
                float4 o1, o2;
                #pragma unroll
                for (int e = 0; e < 4; ++e) {
                    const int f = f4 + e;
                    const float v1 = cr[f] * sc;
                    const float v2 = cr[f + 64] * sc;
                    const float cz = rp[2*f], sz = rp[2*f + 1];
                    float r1 =  v1 * cz + v2 * sz;
                    float r2 = -v1 * sz + v2 * cz;
                    if (rnd) { r1 = rna_tf32(r1); r2 = rna_tf32(r2); }
                    (&o1.x)[e] = r1;
                    (&o2.x)[e] = r2;
                }
                *(float4*)(op + f4)      = o1;
                *(float4*)(op + f4 + 64) = o2;
            }
        }
        __syncthreads();   // Cs reads done before smem reuse
    }
};

// ---------------------------------------------------------------------------
// GRIDDED merged q/k/v GEMM (proven config). A = raw x; CVT_A rounds frags.
// grid (24, 64): bx 0..15 -> q (fuse), 16..19 -> k (fuse+round), 20..23 -> v.
// ---------------------------------------------------------------------------
__global__ __launch_bounds__(128, 2)
void tc_gemm_qkv(const float* __restrict__ A,
                 const float* __restrict__ Wq, const float* __restrict__ Wk,
                 const float* __restrict__ Wv,
                 float* __restrict__ Cq, float* __restrict__ Ck, float* __restrict__ Cv,
                 const float* __restrict__ rope)
{
    extern __shared__ float smf[];
    const int bxg = blockIdx.x, by = blockIdx.y;

    const float* Wbase; float* Cout; int N, bxl; bool fuse, rnd;
    if (bxg < 16)      { Wbase = Wq; Cout = Cq; N = NQ_;  bxl = bxg;      fuse = true;  rnd = false; }
    else if (bxg < 20) { Wbase = Wk; Cout = Ck; N = NKV_; bxl = bxg - 16; fuse = true;  rnd = true;  }
    else               { Wbase = Wv; Cout = Cv; N = NKV_; bxl = bxg - 20; fuse = false; rnd = true;  }

    GemmCore core;
    core.smf = smf; core.sbase = smem_u32(smf);
    core.tid = threadIdx.x;
    const int lane = core.tid & 31;
    const int wid  = core.tid >> 5;
    core.warp_m = wid >> 1; core.warp_n = wid & 1;
    core.g = lane >> 2; core.q4 = lane & 3;
    core.Ab = A + (size_t)(by * 128) * DM_;
    core.Wb = Wbase + (size_t)(bxl * 128) * DM_;

    float acc[4][8][4];
    #pragma unroll
    for (int mi = 0; mi < 4; ++mi)
        #pragma unroll
        for (int ni = 0; ni < 8; ++ni)
            #pragma unroll
            for (int e = 0; e < 4; ++e) acc[mi][ni][e] = 0.f;

    core.mainloop<true>(acc, DM_);   // round A-frags (x is raw fp32)

    if (fuse) core.epilogue_fuse (acc, Cout, N, by * 128, bxl * 128, rope, rnd);
    else      core.epilogue_plain(acc, Cout, N, by * 128, bxl * 128, rnd);
}

// PERSISTENT Wo projection GEMM (measured 407 us, tensor 64%).
// A = att, already tf32-rounded by flash -> no frag cvt.
__global__ __launch_bounds__(128, 2)
void tc_gemm_wo(const float* __restrict__ A, const float* __restrict__ W,
                float* __restrict__ C)
{
    extern __shared__ float smf[];

    GemmCore core;
    core.smf = smf; core.sbase = smem_u32(smf);
    core.tid = threadIdx.x;
    const int lane = core.tid & 31;
    const int wid  = core.tid >> 5;
    core.warp_m = wid >> 1; core.warp_n = wid & 1;
    core.g = lane >> 2; core.q4 = lane & 3;

    const int NT = (NQ_/128) * (M_/128);
    for (int tile = blockIdx.x; tile < NT; tile += NSM_SLOTS) {
        const int bx = tile % (NQ_/128);
        const int by = tile / (NQ_/128);

        core.Ab = A + (size_t)(by * 128) * DM_;
        core.Wb = W + (size_t)(bx * 128) * DM_;

        float acc[4][8][4];
        #pragma unroll
        for (int mi = 0; mi < 4; ++mi)
            #pragma unroll
            for (int ni = 0; ni < 8; ++ni)
                #pragma unroll
                for (int e = 0; e < 4; ++e) acc[mi][ni][e] = 0.f;

        core.mainloop<false>(acc, DM_);
        core.epilogue_plain(acc, C, NQ_, by * 128, bx * 128, false);
    }
}

// ---------------------------------------------------------------------------
// Tensor-core flash attention (tf32 mma.sync), causal, GQA. (proven)
// ---------------------------------------------------------------------------
#define FKV 8704   // floats per K/V buffer (64*136)

__global__ __launch_bounds__(256, 1)
void flash_tc(const float* __restrict__ Q, const float* __restrict__ K,
              const float* __restrict__ V, float* __restrict__ Out)
{
    extern __shared__ float sm[];
    float* Psm = sm;                       // 128 x 68
    float* Ks0 = sm + FKV;                 // 64 x 136
    float* Ks1 = sm + 2*FKV;
    float* Vs0 = sm + 3*FKV;
    float* Vs1 = sm + 4*FKV;
    const uint32_t sb = smem_u32(sm);

    const int qt  = (int)gridDim.x - 1 - (int)blockIdx.x;
    const int h   = blockIdx.y;
    const int b   = blockIdx.z;
    const int kvh = h >> 2;
    const int tid = threadIdx.x;
    const int lane = tid & 31;
    const int wm   = tid >> 5;
    const int g    = lane >> 2;
    const int q4   = lane & 3;

    const float scale = 0.08838834764831843f;

    {   // stage Q tile (128 x 128) into K0+K1 region, stride 136
        const float* qp = Q + (size_t)(b*T_ + qt*128) * NQ_ + h*128;
        uint32_t qdst = sb + FKV*4;
        #pragma unroll
        for (int it = 0; it < 16; ++it) {
            int idx = it * 256 + tid;
            int row = idx >> 5, seg = idx & 31;
            CP_ASYNC16(qdst + ((uint32_t)row*136 + seg*4)*4, qp + (size_t)row*NQ_ + seg*4);
        }
        CP_COMMIT();
        CP_WAIT(0);
        __syncthreads();
    }

    uint32_t qf[16][4];
    {
        const float* qs = Ks0 + (wm*16 + g)*136 + 2*q4;
        #pragma unroll
        for (int ks = 0; ks < 16; ++ks) {
            float2 t0 = *(const float2*)(qs + ks*8);
            float2 t1 = *(const float2*)(qs + ks*8 + 8*136);
            qf[ks][0] = rna_tf32_u(t0.x * scale);
            qf[ks][2] = rna_tf32_u(t0.y * scale);
            qf[ks][1] = rna_tf32_u(t1.x * scale);
            qf[ks][3] = rna_tf32_u(t1.y * scale);
        }
    }
    __syncthreads();

    const int njt = 2*qt + 2;

    auto load_k = [&](int jt) {
        uint32_t kd = sb + (uint32_t)((jt & 1) ? 2*FKV : FKV) * 4;
        const float* kp = K + (size_t)(b*T_ + jt*64) * NKV_ + kvh*128;
        #pragma unroll
        for (int it = 0; it < 8; ++it) {
            int idx = it * 256 + tid;
            int row = idx >> 5, seg = idx & 31;
            CP_ASYNC16(kd + ((uint32_t)row*136 + seg*4)*4, kp + (size_t)row*NKV_ + seg*4);
        }
    };
    auto load_v = [&](int jt) {
        uint32_t vd = sb + (uint32_t)((jt & 1) ? 4*FKV : 3*FKV) * 4;
        const float* vp = V + (size_t)(b*T_ + jt*64) * NKV_ + kvh*128;
        #pragma unroll
        for (int it = 0; it < 8; ++it) {
            int idx = it * 256 + tid;
            int row = idx >> 5, seg = idx & 31;
            CP_ASYNC16(vd + ((uint32_t)row*136 + seg*4)*4, vp + (size_t)row*NKV_ + seg*4);
        }
    };

    load_k(0); load_v(0); CP_COMMIT();
    load_k(1); load_v(1); CP_COMMIT();

    float m0 = -1e30f, m1 = -1e30f, l0 = 0.f, l1 = 0.f;
    float O[16][4];
    #pragma unroll
    for (int nf = 0; nf < 16; ++nf)
        #pragma unroll
        for (int e = 0; e < 4; ++e) O[nf][e] = 0.f;

    const int row_g0 = qt*128 + wm*16 + g;
    float* Prow = Psm + (wm*16 + g)*68;

    for (int jt = 0; jt < njt; ++jt) {
        const int cur = jt & 1;
        if (jt == 0) { CP_WAIT(1); } else { CP_WAIT(2); }
        __syncthreads();

        const float* Kc = cur ? Ks1 : Ks0;
        const float* Vc = cur ? Vs1 : Vs0;

        float S[8][4];
        #pragma unroll
        for (int nf = 0; nf < 8; ++nf)
            #pragma unroll
            for (int e = 0; e < 4; ++e) S[nf][e] = 0.f;

        #pragma unroll
        for (int ks = 0; ks < 16; ++ks) {
            const float* kb = Kc + g*136 + ks*8 + 2*q4;
            #pragma unroll
            for (int nf = 0; nf < 8; ++nf) {
                float2 t = *(const float2*)(kb + nf*8*136);
                uint32_t bb[2] = { __float_as_uint(t.x), __float_as_uint(t.y) };
                MMA_TF32(S[nf], qf[ks], bb);
            }
        }

        if (jt >= 2*qt) {
            const int colb = jt*64 + 2*q4;
            #pragma unroll
            for (int nf = 0; nf < 8; ++nf) {
                const int c0 = colb + nf*8;
                if (c0     > row_g0)     S[nf][0] = -1e30f;
                if (c0 + 1 > row_g0)     S[nf][1] = -1e30f;
                if (c0     > row_g0 + 8) S[nf][2] = -1e30f;
                if (c0 + 1 > row_g0 + 8) S[nf][3] = -1e30f;
            }
        }

        float rm0 = -1e30f, rm1 = -1e30f;
        #pragma unroll
        for (int nf = 0; nf < 8; ++nf) {
            rm0 = fmaxf(rm0, fmaxf(S[nf][0], S[nf][1]));
            rm1 = fmaxf(rm1, fmaxf(S[nf][2], S[nf][3]));
        }
        rm0 = fmaxf(rm0, __shfl_xor_sync(0xffffffffu, rm0, 1));
        rm0 = fmaxf(rm0, __shfl_xor_sync(0xffffffffu, rm0, 2));
        rm1 = fmaxf(rm1, __shfl_xor_sync(0xffffffffu, rm1, 1));
        rm1 = fmaxf(rm1, __shfl_xor_sync(0xffffffffu, rm1, 2));

        const float mn0 = fmaxf(m0, rm0), mn1 = fmaxf(m1, rm1);
        const float corr0 = __expf(m0 - mn0), corr1 = __expf(m1 - mn1);
        m0 = mn0; m1 = mn1;

        float rs0 = 0.f, rs1 = 0.f;
        #pragma unroll
        for (int nf = 0; nf < 8; ++nf) {
            S[nf][0] = __expf(S[nf][0] - mn0);
            S[nf][1] = __expf(S[nf][1] - mn0);
            S[nf][2] = __expf(S[nf][2] - mn1);
            S[nf][3] = __expf(S[nf][3] - mn1);
            rs0 += S[nf][0] + S[nf][1];
            rs1 += S[nf][2] + S[nf][3];
        }
        rs0 += __shfl_xor_sync(0xffffffffu, rs0, 1);
        rs0 += __shfl_xor_sync(0xffffffffu, rs0, 2);
        rs1 += __shfl_xor_sync(0xffffffffu, rs1, 1);
        rs1 += __shfl_xor_sync(0xffffffffu, rs1, 2);
        l0 = l0*corr0 + rs0;
        l1 = l1*corr1 + rs1;

        #pragma unroll
        for (int nf = 0; nf < 16; ++nf) {
            O[nf][0] *= corr0; O[nf][1] *= corr0;
            O[nf][2] *= corr1; O[nf][3] *= corr1;
        }

        #pragma unroll
        for (int nf = 0; nf < 8; ++nf) {
            const int c = nf*8 + 2*q4;
            *(float2*)(Prow + c)        = make_float2(rna_tf32(S[nf][0]), rna_tf32(S[nf][1]));
            *(float2*)(Prow + 8*68 + c) = make_float2(rna_tf32(S[nf][2]), rna_tf32(S[nf][3]));
        }
        __syncthreads();

        if (jt + 2 < njt) load_k(jt + 2);
        CP_COMMIT();

        #pragma unroll
        for (int ks = 0; ks < 8; ++ks) {
            uint32_t a[4];
            a[0] = __float_as_uint(Prow[ks*8 + q4]);
            a[2] = __float_as_uint(Prow[ks*8 + q4 + 4]);
            a[1] = __float_as_uint(Prow[8*68 + ks*8 + q4]);
            a[3] = __float_as_uint(Prow[8*68 + ks*8 + q4 + 4]);
            const float* vb = Vc + (ks*8 + q4)*136 + g;
            #pragma unroll
            for (int nf = 0; nf < 16; ++nf) {
                uint32_t bb[2] = { __float_as_uint(vb[nf*8]),
                                   __float_as_uint(vb[nf*8 + 4*136]) };
                MMA_TF32(O[nf], a, bb);
            }
        }
        __syncthreads();

        if (jt + 2 < njt) load_v(jt + 2);
        CP_COMMIT();
    }

    const float inv0 = 1.0f / l0;
    const float inv1 = 1.0f / l1;
    float* o0 = Out + (size_t)(b*T_ + row_g0)     * NQ_ + h*128 + 2*q4;
    float* o1 = Out + (size_t)(b*T_ + row_g0 + 8) * NQ_ + h*128 + 2*q4;
    #pragma unroll
    for (int nf = 0; nf < 16; ++nf) {
        *(float2*)(o0 + nf*8) = make_float2(rna_tf32(O[nf][0]*inv0), rna_tf32(O[nf][1]*inv0));
        *(float2*)(o1 + nf*8) = make_float2(rna_tf32(O[nf][2]*inv1), rna_tf32(O[nf][3]*inv1));
    }
}

// ---------------------------------------------------------------------------
__global__ void zero_tail_kernel(float* __restrict__ out, long start, long total) {
    long idx = start + blockIdx.x * (long)blockDim.x + threadIdx.x;
    if (idx < total) out[idx] = 0.f;
}

// ---------------------------------------------------------------------------
extern "C" void kernel_launch(void* const* d_in, const int* in_sizes, int n_in,
                              void* d_out, int out_size) {
    const float* x  = (const float*)d_in[0];
    const float* Wq = (const float*)d_in[1];
    const float* Wk = (const float*)d_in[2];
    const float* Wv = (const float*)d_in[3];
    const float* Wo = (const float*)d_in[4];
    float* out = (float*)d_out;

    float *q, *k, *v, *att, *wq, *wk, *wv, *wo, *rope;
    cudaGetSymbolAddress((void**)&q,    g_q);
    cudaGetSymbolAddress((void**)&k,    g_k);
    cudaGetSymbolAddress((void**)&v,    g_v);
    cudaGetSymbolAddress((void**)&att,  g_att);
    cudaGetSymbolAddress((void**)&wq,   g_wq);
    cudaGetSymbolAddress((void**)&wk,   g_wk);
    cudaGetSymbolAddress((void**)&wv,   g_wv);
    cudaGetSymbolAddress((void**)&wo,   g_wo);
    cudaGetSymbolAddress((void**)&rope, g_rope);

    // Launches: 1 prepass (W only), 2 qkv GEMM (gridded, frag-cvt A),
    //           3 flash, 4 Wo GEMM (persistent), 5 tail.
    const long n_f4 = (2L*NQ_*DM_ + 2L*NKV_*DM_) / 4;
    const long total_thr = n_f4 + (long)T_*64;
    prepass_all_kernel<<<(int)((total_thr + 255)/256), 256>>>(
        Wq, Wk, Wv, Wo, wq, wk, wv, wo, rope);

    const int gsm = 2 * STAGE_B;   // 81920 B -> two CTAs per SM
    cudaFuncSetAttribute(tc_gemm_qkv, cudaFuncAttributeMaxDynamicSharedMemorySize, gsm);
    cudaFuncSetAttribute(tc_gemm_wo,  cudaFuncAttributeMaxDynamicSharedMemorySize, gsm);

    tc_gemm_qkv<<<dim3(24, M_/128), dim3(128), gsm>>>(x, wq, wk, wv, q, k, v, rope);

    const int fsm = 5 * FKV * 4;   // 174080 B
    cudaFuncSetAttribute(flash_tc, cudaFuncAttributeMaxDynamicSharedMemorySize, fsm);
    flash_tc<<<dim3(T_/128, H_, B_), dim3(256), fsm>>>(q, k, v, att);

    tc_gemm_wo<<<NSM_SLOTS, dim3(128), gsm>>>(att, wo, out);

    long main_elems = (long)M_ * NQ_;
    long tail = (long)out_size - main_elems;
    if (tail > 0) {
        int nb = (int)((tail + 255) / 256);
        zero_tail_kernel<<<nb, 256>>>(out, main_elems, (long)out_size);
    }
}

// round 16
// speedup vs baseline: 1.0230x; 1.0230x over previous
#include <cuda_runtime.h>
#include <math.h>
#include <stdint.h>

// Problem constants
#define B_    4
#define T_    2048
#define DM_   2048
#define H_    16
#define HKV_  4
#define D_    128
#define M_    (B_*T_)      // 8192 tokens
#define NQ_   (H_*D_)      // 2048
#define NKV_  (HKV_*D_)    // 512

#define NSM_SLOTS 296      // 148 SMs x 2 CTAs (persistent Wo GEMM grid)

// Scratch (device globals: allocation-free per harness rules)
__device__ float g_q  [M_*NQ_];
__device__ float g_k  [M_*NKV_];
__device__ float g_v  [M_*NKV_];
__device__ float g_att[M_*NQ_];
__device__ float g_xr [M_*DM_];
__device__ float g_wq [NQ_*DM_];
__device__ float g_wk [NKV_*DM_];
__device__ float g_wv [NKV_*DM_];
__device__ float g_wo [DM_*NQ_];
__device__ float g_rope[T_*64*2];

// ---------------------------------------------------------------------------
// Helpers
// ---------------------------------------------------------------------------
__device__ __forceinline__ uint32_t smem_u32(const void* p) {
    uint32_t a;
    asm("{ .reg .u64 t; cvta.to.shared.u64 t, %1; cvt.u32.u64 %0, t; }" : "=r"(a) : "l"(p));
    return a;
}
__device__ __forceinline__ float rna_tf32(float v) {
    uint32_t b;
    asm("cvt.rna.tf32.f32 %0, %1;" : "=r"(b) : "f"(v));
    return __uint_as_float(b);
}
__device__ __forceinline__ uint32_t rna_tf32_u(float v) {
    uint32_t b;
    asm("cvt.rna.tf32.f32 %0, %1;" : "=r"(b) : "f"(v));
    return b;
}
__device__ __forceinline__ float ex2f(float v) {   // exp2, single MUFU op
    float r;
    asm("ex2.approx.f32 %0, %1;" : "=f"(r) : "f"(v));
    return r;
}

#define CP_ASYNC16(dst, src) \
    asm volatile("cp.async.cg.shared.global [%0], [%1], 16;" :: "r"(dst), "l"(src) : "memory")
#define CP_COMMIT()  asm volatile("cp.async.commit_group;" ::: "memory")
#define CP_WAIT(n)   asm volatile("cp.async.wait_group %0;" :: "n"(n) : "memory")

// mma.sync m16n8k8 tf32 (family-portable)
#define MMA_TF32(c, a, b) \
    asm volatile("mma.sync.aligned.m16n8k8.row.col.f32.tf32.tf32.f32 " \
        "{%0,%1,%2,%3}, {%4,%5,%6,%7}, {%8,%9}, {%0,%1,%2,%3};" \
        : "+f"((c)[0]), "+f"((c)[1]), "+f"((c)[2]), "+f"((c)[3]) \
        : "r"((a)[0]), "r"((a)[1]), "r"((a)[2]), "r"((a)[3]), \
          "r"((b)[0]), "r"((b)[1]))

// ---------------------------------------------------------------------------
// ONE fused prepass: RNA-round x/Wq/Wk/Wv/Wo + RoPE table, single launch.
// ---------------------------------------------------------------------------
__global__ void prepass_all_kernel(
    const float* __restrict__ x,  const float* __restrict__ Wq,
    const float* __restrict__ Wk, const float* __restrict__ Wv,
    const float* __restrict__ Wo,
    float* __restrict__ oxr, float* __restrict__ owq, float* __restrict__ owk,
    float* __restrict__ owv, float* __restrict__ owo, float* __restrict__ rope)
{
    const long n_x  = (long)M_  * DM_ / 4;
    const long n_q  = (long)NQ_ * DM_ / 4;
    const long n_kv = (long)NKV_* DM_ / 4;
    const long n_f4 = n_x + 2*n_q + 2*n_kv;
    long j = blockIdx.x * (long)blockDim.x + threadIdx.x;

    if (j < n_f4) {
        const float* src; float* dst; long i = j;
        if (i < n_x)                 { src = x;  dst = oxr; }
        else if ((i -= n_x) < n_q)   { src = Wq; dst = owq; }
        else if ((i -= n_q) < n_kv)  { src = Wk; dst = owk; }
        else if ((i -= n_kv) < n_kv) { src = Wv; dst = owv; }
        else                         { i -= n_kv; src = Wo; dst = owo; }
        float4 v = ((const float4*)src)[i];
        v.x = rna_tf32(v.x); v.y = rna_tf32(v.y); v.z = rna_tf32(v.z); v.w = rna_tf32(v.w);
        ((float4*)dst)[i] = v;
        return;
    }
    long r = j - n_f4;
    if (r < (long)T_ * 64) {
        int t = (int)(r >> 6), f = (int)(r & 63);
        double invf = exp(-((double)f / 64.0) * log(10000.0));
        float ang = (float)t * (float)invf;
        rope[r*2 + 0] = (float)cos((double)ang);
        rope[r*2 + 1] = (float)sin((double)ang);
    }
}

// ---------------------------------------------------------------------------
// GEMM core: CTA 128x128x32, 4 warps (64x64 warp tiles), 2 CTAs/SM.
// Proven 2-stage stride-40 mainloop.
// ---------------------------------------------------------------------------
#define STAGE_F 10240
#define STAGE_B (STAGE_F*4)

struct GemmCore {
    const float* Ab;
    const float* Wb;
    float* smf;
    uint32_t sbase;
    int tid, warp_m, warp_n, g, q4;

    __device__ __forceinline__ void load_stage(int s, int kt, int K) const {
        uint32_t aS = sbase + s * STAGE_B;
        uint32_t bS = aS + 20480;
        const float* ap = Ab + kt * 32;
        const float* wp = Wb + kt * 32;
        #pragma unroll
        for (int it = 0; it < 8; ++it) {
            int idx = it * 128 + tid;
            int row = idx >> 3, seg = idx & 7;
            uint32_t so = (uint32_t)row * 160 + (uint32_t)seg * 16;
            CP_ASYNC16(aS + so, ap + (size_t)row * K + seg * 4);
            CP_ASYNC16(bS + so, wp + (size_t)row * K + seg * 4);
        }
    }

    __device__ __forceinline__ void load_frags(const float* As_, const float* Bs_,
                                               int ks, uint32_t* a, uint32_t* b) const {
        const int col = ks * 8 + 2 * q4;
        #pragma unroll
        for (int ni = 0; ni < 8; ++ni) {
            float2 t = *(const float2*)&Bs_[(ni * 8 + g) * 40 + col];
            b[ni*2]   = __float_as_uint(t.x);
            b[ni*2+1] = __float_as_uint(t.y);
        }
        #pragma unroll
        for (int mi = 0; mi < 4; ++mi) {
            float2 t0 = *(const float2*)&As_[(mi * 16 + g) * 40 + col];
            float2 t1 = *(const float2*)&As_[(mi * 16 + g + 8) * 40 + col];
            a[mi*4+0] = __float_as_uint(t0.x);
            a[mi*4+2] = __float_as_uint(t0.y);
            a[mi*4+1] = __float_as_uint(t1.x);
            a[mi*4+3] = __float_as_uint(t1.y);
        }
    }

    __device__ __forceinline__ void mainloop(float acc[4][8][4], int K) const {
        const int KT = K >> 5;
        load_stage(0, 0, K);
        CP_COMMIT();
        for (int kt = 0; kt < KT; ++kt) {
            const int cur = kt & 1;
            CP_WAIT(0);
            __syncthreads();
            if (kt + 1 < KT) {
                load_stage(cur ^ 1, kt + 1, K);
                CP_COMMIT();
            }
            const float* As_ = smf + cur * STAGE_F + warp_m * (64 * 40);
            const float* Bs_ = smf + cur * STAGE_F + 5120 + warp_n * (64 * 40);

            uint32_t aF[2][16], bF[2][16];
            load_frags(As_, Bs_, 0, aF[0], bF[0]);
            #pragma unroll
            for (int ks = 0; ks < 4; ++ks) {
                const int cb = ks & 1;
                if (ks < 3) load_frags(As_, Bs_, ks + 1, aF[cb ^ 1], bF[cb ^ 1]);
                #pragma unroll
                for (int mi = 0; mi < 4; ++mi)
                    #pragma unroll
                    for (int ni = 0; ni < 8; ++ni)
                        MMA_TF32(acc[mi][ni], &aF[cb][mi*4], &bF[cb][ni*2]);
            }
        }
        __syncthreads();   // all reads done; stage smem reusable
    }

    __device__ __forceinline__ void epilogue_plain(float acc[4][8][4], float* C,
                                                   int N, int row0, int col0, bool rnd) const {
        #pragma unroll
        for (int mi = 0; mi < 4; ++mi) {
            const int r = row0 + warp_m * 64 + mi * 16 + g;
            #pragma unroll
            for (int ni = 0; ni < 8; ++ni) {
                const int c = col0 + warp_n * 64 + ni * 8 + q4 * 2;
                float e0 = acc[mi][ni][0], e1 = acc[mi][ni][1];
                float e2 = acc[mi][ni][2], e3 = acc[mi][ni][3];
                if (rnd) { e0 = rna_tf32(e0); e1 = rna_tf32(e1); e2 = rna_tf32(e2); e3 = rna_tf32(e3); }
                *(float2*)&C[(size_t)r * N + c]       = make_float2(e0, e1);
                *(float2*)&C[(size_t)(r + 8) * N + c] = make_float2(e2, e3);
            }
        }
    }

    __device__ __forceinline__ void epilogue_fuse(float acc[4][8][4], float* C,
                                                  int N, int row0, int col0,
                                                  const float* rope, bool rnd) const {
        float* Cs = smf;   // 128*129 floats = 66048 B <= 2*STAGE_B (stages idle)
        #pragma unroll
        for (int mi = 0; mi < 4; ++mi) {
            const int r = warp_m * 64 + mi * 16 + g;
            #pragma unroll
            for (int ni = 0; ni < 8; ++ni) {
                const int c = warp_n * 64 + ni * 8 + q4 * 2;
                Cs[r * 129 + c]           = acc[mi][ni][0];
                Cs[r * 129 + c + 1]       = acc[mi][ni][1];
                Cs[(r + 8) * 129 + c]     = acc[mi][ni][2];
                Cs[(r + 8) * 129 + c + 1] = acc[mi][ni][3];
            }
        }
        __syncthreads();
        {
            const int row = row0 + tid;          // 128 threads = 128 rows
            const float* cr = Cs + tid * 129;
            float ss = 0.f;
            #pragma unroll 16
            for (int j = 0; j < 128; ++j) ss += cr[j] * cr[j];
            const float sc = rsqrtf(ss * (1.0f/128.0f) + 1.1920928955078125e-07f);
            const float* rp = rope + (row & (T_ - 1)) * 128;
            float* op = C + (size_t)row * N + col0;
            #pragma unroll
            for (int f4 = 0; f4 < 64; f4 += 4) {
                float4 o1, o2;
                #pragma unroll
                for (int e = 0; e < 4; ++e) {
                    const int f = f4 + e;
                    const float v1 = cr[f] * sc;
                    const float v2 = cr[f + 64] * sc;
                    const float cz = rp[2*f], sz = rp[2*f + 1];
                    float r1 =  v1 * cz + v2 * sz;
                    float r2 = -v1 * sz + v2 * cz;
                    if (rnd) { r1 = rna_tf32(r1); r2 = rna_tf32(r2); }
                    (&o1.x)[e] = r1;
                    (&o2.x)[e] = r2;
                }
                *(float4*)(op + f4)      = o1;
                *(float4*)(op + f4 + 64) = o2;
            }
        }
        __syncthreads();   // Cs reads done before smem reuse
    }
};

// ---------------------------------------------------------------------------
// GRIDDED merged q/k/v GEMM (proven config, prepass-rounded inputs).
// grid (24, 64): bx 0..15 -> q (fuse), 16..19 -> k (fuse+round), 20..23 -> v.
// ---------------------------------------------------------------------------
__global__ __launch_bounds__(128, 2)
void tc_gemm_qkv(const float* __restrict__ A,
                 const float* __restrict__ Wq, const float* __restrict__ Wk,
                 const float* __restrict__ Wv,
                 float* __restrict__ Cq, float* __restrict__ Ck, float* __restrict__ Cv,
                 const float* __restrict__ rope)
{
    extern __shared__ float smf[];
    const int bxg = blockIdx.x, by = blockIdx.y;

    const float* Wbase; float* Cout; int N, bxl; bool fuse, rnd;
    if (bxg < 16)      { Wbase = Wq; Cout = Cq; N = NQ_;  bxl = bxg;      fuse = true;  rnd = false; }
    else if (bxg < 20) { Wbase = Wk; Cout = Ck; N = NKV_; bxl = bxg - 16; fuse = true;  rnd = true;  }
    else               { Wbase = Wv; Cout = Cv; N = NKV_; bxl = bxg - 20; fuse = false; rnd = true;  }

    GemmCore core;
    core.smf = smf; core.sbase = smem_u32(smf);
    core.tid = threadIdx.x;
    const int lane = core.tid & 31;
    const int wid  = core.tid >> 5;
    core.warp_m = wid >> 1; core.warp_n = wid & 1;
    core.g = lane >> 2; core.q4 = lane & 3;
    core.Ab = A + (size_t)(by * 128) * DM_;
    core.Wb = Wbase + (size_t)(bxl * 128) * DM_;

    float acc[4][8][4];
    #pragma unroll
    for (int mi = 0; mi < 4; ++mi)
        #pragma unroll
        for (int ni = 0; ni < 8; ++ni)
            #pragma unroll
            for (int e = 0; e < 4; ++e) acc[mi][ni][e] = 0.f;

    core.mainloop(acc, DM_);

    if (fuse) core.epilogue_fuse (acc, Cout, N, by * 128, bxl * 128, rope, rnd);
    else      core.epilogue_plain(acc, Cout, N, by * 128, bxl * 128, rnd);
}

// PERSISTENT Wo projection GEMM (measured 407 us, tensor 64%).
__global__ __launch_bounds__(128, 2)
void tc_gemm_wo(const float* __restrict__ A, const float* __restrict__ W,
                float* __restrict__ C)
{
    extern __shared__ float smf[];

    GemmCore core;
    core.smf = smf; core.sbase = smem_u32(smf);
    core.tid = threadIdx.x;
    const int lane = core.tid & 31;
    const int wid  = core.tid >> 5;
    core.warp_m = wid >> 1; core.warp_n = wid & 1;
    core.g = lane >> 2; core.q4 = lane & 3;

    const int NT = (NQ_/128) * (M_/128);
    for (int tile = blockIdx.x; tile < NT; tile += NSM_SLOTS) {
        const int bx = tile % (NQ_/128);
        const int by = tile / (NQ_/128);

        core.Ab = A + (size_t)(by * 128) * DM_;
        core.Wb = W + (size_t)(bx * 128) * DM_;

        float acc[4][8][4];
        #pragma unroll
        for (int mi = 0; mi < 4; ++mi)
            #pragma unroll
            for (int ni = 0; ni < 8; ++ni)
                #pragma unroll
                for (int e = 0; e < 4; ++e) acc[mi][ni][e] = 0.f;

        core.mainloop(acc, DM_);
        core.epilogue_plain(acc, C, NQ_, by * 128, bx * 128, false);
    }
}

// ---------------------------------------------------------------------------
// Tensor-core flash attention (tf32 mma.sync), causal, GQA.
// R15 changes: exp2 domain (log2e folded into Q scale, ex2.approx MUFU),
// 2 barriers/iter (P round-trip is intra-warp -> __syncwarp; K+V prefetch
// moved behind the post-PV barrier, one combined commit group per iter),
// conditional O-rescale (skipped when no row max increased, exact).
// ---------------------------------------------------------------------------
#define FKV 8704   // floats per K/V buffer (64*136)

__global__ __launch_bounds__(256, 1)
void flash_tc(const float* __restrict__ Q, const float* __restrict__ K,
              const float* __restrict__ V, float* __restrict__ Out)
{
    extern __shared__ float sm[];
    float* Psm = sm;                       // 128 x 68
    float* Ks0 = sm + FKV;                 // 64 x 136
    float* Ks1 = sm + 2*FKV;
    float* Vs0 = sm + 3*FKV;
    float* Vs1 = sm + 4*FKV;
    const uint32_t sb = smem_u32(sm);

    const int qt  = (int)gridDim.x - 1 - (int)blockIdx.x;
    const int h   = blockIdx.y;
    const int b   = blockIdx.z;
    const int kvh = h >> 2;
    const int tid = threadIdx.x;
    const int lane = tid & 31;
    const int wm   = tid >> 5;
    const int g    = lane >> 2;
    const int q4   = lane & 3;

    // 1/sqrt(128) * log2(e): S computed directly in log2 domain
    const float scale2 = 0.08838834764831843f * 1.4426950408889634f;

    {   // stage Q tile (128 x 128) into K0+K1 region, stride 136
        const float* qp = Q + (size_t)(b*T_ + qt*128) * NQ_ + h*128;
        uint32_t qdst = sb + FKV*4;
        #pragma unroll
        for (int it = 0; it < 16; ++it) {
            int idx = it * 256 + tid;
            int row = idx >> 5, seg = idx & 31;
            CP_ASYNC16(qdst + ((uint32_t)row*136 + seg*4)*4, qp + (size_t)row*NQ_ + seg*4);
        }
        CP_COMMIT();
        CP_WAIT(0);
        __syncthreads();
    }

    uint32_t qf[16][4];
    {
        const float* qs = Ks0 + (wm*16 + g)*136 + 2*q4;
        #pragma unroll
        for (int ks = 0; ks < 16; ++ks) {
            float2 t0 = *(const float2*)(qs + ks*8);
            float2 t1 = *(const float2*)(qs + ks*8 + 8*136);
            qf[ks][0] = rna_tf32_u(t0.x * scale2);
            qf[ks][2] = rna_tf32_u(t0.y * scale2);
            qf[ks][1] = rna_tf32_u(t1.x * scale2);
            qf[ks][3] = rna_tf32_u(t1.y * scale2);
        }
    }
    __syncthreads();

    const int njt = 2*qt + 2;

    auto load_k = [&](int jt) {
        uint32_t kd = sb + (uint32_t)((jt & 1) ? 2*FKV : FKV) * 4;
        const float* kp = K + (size_t)(b*T_ + jt*64) * NKV_ + kvh*128;
        #pragma unroll
        for (int it = 0; it < 8; ++it) {
            int idx = it * 256 + tid;
            int row = idx >> 5, seg = idx & 31;
            CP_ASYNC16(kd + ((uint32_t)row*136 + seg*4)*4, kp + (size_t)row*NKV_ + seg*4);
        }
    };
    auto load_v = [&](int jt) {
        uint32_t vd = sb + (uint32_t)((jt & 1) ? 4*FKV : 3*FKV) * 4;
        const float* vp = V + (size_t)(b*T_ + jt*64) * NKV_ + kvh*128;
        #pragma unroll
        for (int it = 0; it < 8; ++it) {
            int idx = it * 256 + tid;
            int row = idx >> 5, seg = idx & 31;
            CP_ASYNC16(vd + ((uint32_t)row*136 + seg*4)*4, vp + (size_t)row*NKV_ + seg*4);
        }
    };

    // prologue: combined K+V group per tile
    load_k(0); load_v(0); CP_COMMIT();
    load_k(1); load_v(1); CP_COMMIT();

    float m0 = -1e30f, m1 = -1e30f, l0 = 0.f, l1 = 0.f;
    float O[16][4];
    #pragma unroll
    for (int nf = 0; nf < 16; ++nf)
        #pragma unroll
        for (int e = 0; e < 4; ++e) O[nf][e] = 0.f;

    const int row_g0 = qt*128 + wm*16 + g;
    float* Prow = Psm + (wm*16 + g)*68;

    for (int jt = 0; jt < njt; ++jt) {
        const int cur = jt & 1;
        CP_WAIT(1);        // group jt complete (newest pending is jt+1 / empty)
        __syncthreads();   // barrier A: K/V[cur] visible; prior readers done

        const float* Kc = cur ? Ks1 : Ks0;
        const float* Vc = cur ? Vs1 : Vs0;

        float S[8][4];
        #pragma unroll
        for (int nf = 0; nf < 8; ++nf)
            #pragma unroll
            for (int e = 0; e < 4; ++e) S[nf][e] = 0.f;

        #pragma unroll
        for (int ks = 0; ks < 16; ++ks) {
            const float* kb = Kc + g*136 + ks*8 + 2*q4;
            #pragma unroll
            for (int nf = 0; nf < 8; ++nf) {
                float2 t = *(const float2*)(kb + nf*8*136);
                uint32_t bb[2] = { __float_as_uint(t.x), __float_as_uint(t.y) };
                MMA_TF32(S[nf], qf[ks], bb);
            }
        }

        if (jt >= 2*qt) {
            const int colb = jt*64 + 2*q4;
            #pragma unroll
            for (int nf = 0; nf < 8; ++nf) {
                const int c0 = colb + nf*8;
                if (c0     > row_g0)     S[nf][0] = -1e30f;
                if (c0 + 1 > row_g0)     S[nf][1] = -1e30f;
                if (c0     > row_g0 + 8) S[nf][2] = -1e30f;
                if (c0 + 1 > row_g0 + 8) S[nf][3] = -1e30f;
            }
        }

        float rm0 = -1e30f, rm1 = -1e30f;
        #pragma unroll
        for (int nf = 0; nf < 8; ++nf) {
            rm0 = fmaxf(rm0, fmaxf(S[nf][0], S[nf][1]));
            rm1 = fmaxf(rm1, fmaxf(S[nf][2], S[nf][3]));
        }
        rm0 = fmaxf(rm0, __shfl_xor_sync(0xffffffffu, rm0, 1));
        rm0 = fmaxf(rm0, __shfl_xor_sync(0xffffffffu, rm0, 2));
        rm1 = fmaxf(rm1, __shfl_xor_sync(0xffffffffu, rm1, 1));
        rm1 = fmaxf(rm1, __shfl_xor_sync(0xffffffffu, rm1, 2));

        const float mn0 = fmaxf(m0, rm0), mn1 = fmaxf(m1, rm1);
        const bool chg = __any_sync(0xffffffffu, (mn0 > m0) | (mn1 > m1));

        float rs0 = 0.f, rs1 = 0.f;
        #pragma unroll
        for (int nf = 0; nf < 8; ++nf) {
            S[nf][0] = ex2f(S[nf][0] - mn0);
            S[nf][1] = ex2f(S[nf][1] - mn0);
            S[nf][2] = ex2f(S[nf][2] - mn1);
            S[nf][3] = ex2f(S[nf][3] - mn1);
            rs0 += S[nf][0] + S[nf][1];
            rs1 += S[nf][2] + S[nf][3];
        }
        rs0 += __shfl_xor_sync(0xffffffffu, rs0, 1);
        rs0 += __shfl_xor_sync(0xffffffffu, rs0, 2);
        rs1 += __shfl_xor_sync(0xffffffffu, rs1, 1);
        rs1 += __shfl_xor_sync(0xffffffffu, rs1, 2);

        if (chg) {   // max increased somewhere in this warp: rescale (exact skip)
            const float corr0 = ex2f(m0 - mn0);
            const float corr1 = ex2f(m1 - mn1);
            l0 = l0*corr0 + rs0;
            l1 = l1*corr1 + rs1;
            #pragma unroll
            for (int nf = 0; nf < 16; ++nf) {
                O[nf][0] *= corr0; O[nf][1] *= corr0;
                O[nf][2] *= corr1; O[nf][3] *= corr1;
            }
        } else {
            l0 += rs0;
            l1 += rs1;
        }
        m0 = mn0; m1 = mn1;

        // P write + read is intra-warp (each warp owns its 16 P rows)
        #pragma unroll
        for (int nf = 0; nf < 8; ++nf) {
            const int c = nf*8 + 2*q4;
            *(float2*)(Prow + c)        = make_float2(rna_tf32(S[nf][0]), rna_tf32(S[nf][1]));
            *(float2*)(Prow + 8*68 + c) = make_float2(rna_tf32(S[nf][2]), rna_tf32(S[nf][3]));
        }
        __syncwarp();

        #pragma unroll
        for (int ks = 0; ks < 8; ++ks) {
            uint32_t a[4];
            a[0] = __float_as_uint(Prow[ks*8 + q4]);
            a[2] = __float_as_uint(Prow[ks*8 + q4 + 4]);
            a[1] = __float_as_uint(Prow[8*68 + ks*8 + q4]);
            a[3] = __float_as_uint(Prow[8*68 + ks*8 + q4 + 4]);
            const float* vb = Vc + (ks*8 + q4)*136 + g;
            #pragma unroll
            for (int nf = 0; nf < 16; ++nf) {
                uint32_t bb[2] = { __float_as_uint(vb[nf*8]),
                                   __float_as_uint(vb[nf*8 + 4*136]) };
                MMA_TF32(O[nf], a, bb);
            }
        }
        __syncthreads();   // barrier B: all warps done with K[cur],V[cur]

        if (jt + 2 < njt) { load_k(jt + 2); load_v(jt + 2); }
        CP_COMMIT();       // one group per iter (possibly empty)
    }

    const float inv0 = 1.0f / l0;
    const float inv1 = 1.0f / l1;
    float* o0 = Out + (size_t)(b*T_ + row_g0)     * NQ_ + h*128 + 2*q4;
    float* o1 = Out + (size_t)(b*T_ + row_g0 + 8) * NQ_ + h*128 + 2*q4;
    #pragma unroll
    for (int nf = 0; nf < 16; ++nf) {
        *(float2*)(o0 + nf*8) = make_float2(rna_tf32(O[nf][0]*inv0), rna_tf32(O[nf][1]*inv0));
        *(float2*)(o1 + nf*8) = make_float2(rna_tf32(O[nf][2]*inv1), rna_tf32(O[nf][3]*inv1));
    }
}

// ---------------------------------------------------------------------------
__global__ void zero_tail_kernel(float* __restrict__ out, long start, long total) {
    long idx = start + blockIdx.x * (long)blockDim.x + threadIdx.x;
    if (idx < total) out[idx] = 0.f;
}

// ---------------------------------------------------------------------------
extern "C" void kernel_launch(void* const* d_in, const int* in_sizes, int n_in,
                              void* d_out, int out_size) {
    const float* x  = (const float*)d_in[0];
    const float* Wq = (const float*)d_in[1];
    const float* Wk = (const float*)d_in[2];
    const float* Wv = (const float*)d_in[3];
    const float* Wo = (const float*)d_in[4];
    float* out = (float*)d_out;

    float *q, *k, *v, *att, *xr, *wq, *wk, *wv, *wo, *rope;
    cudaGetSymbolAddress((void**)&q,    g_q);
    cudaGetSymbolAddress((void**)&k,    g_k);
    cudaGetSymbolAddress((void**)&v,    g_v);
    cudaGetSymbolAddress((void**)&att,  g_att);
    cudaGetSymbolAddress((void**)&xr,   g_xr);
    cudaGetSymbolAddress((void**)&wq,   g_wq);
    cudaGetSymbolAddress((void**)&wk,   g_wk);
    cudaGetSymbolAddress((void**)&wv,   g_wv);
    cudaGetSymbolAddress((void**)&wo,   g_wo);
    cudaGetSymbolAddress((void**)&rope, g_rope);

    // Launches: 1 prepass, 2 qkv GEMM (gridded), 3 flash (2-barrier/exp2),
    //           4 Wo GEMM (persistent), 5 tail.
    const long n_f4 = ((long)M_*DM_ + 2L*NQ_*DM_ + 2L*NKV_*DM_) / 4;
    const long total_thr = n_f4 + (long)T_*64;
    prepass_all_kernel<<<(int)((total_thr + 255)/256), 256>>>(
        x, Wq, Wk, Wv, Wo, xr, wq, wk, wv, wo, rope);

    const int gsm = 2 * STAGE_B;   // 81920 B -> two CTAs per SM
    cudaFuncSetAttribute(tc_gemm_qkv, cudaFuncAttributeMaxDynamicSharedMemorySize, gsm);
    cudaFuncSetAttribute(tc_gemm_wo,  cudaFuncAttributeMaxDynamicSharedMemorySize, gsm);

    tc_gemm_qkv<<<dim3(24, M_/128), dim3(128), gsm>>>(xr, wq, wk, wv, q, k, v, rope);

    const int fsm = 5 * FKV * 4;   // 174080 B
    cudaFuncSetAttribute(flash_tc, cudaFuncAttributeMaxDynamicSharedMemorySize, fsm);
    flash_tc<<<dim3(T_/128, H_, B_), dim3(256), fsm>>>(q, k, v, att);

    tc_gemm_wo<<<NSM_SLOTS, dim3(128), gsm>>>(att, wo, out);

    long main_elems = (long)M_ * NQ_;
    long tail = (long)out_size - main_elems;
    if (tail > 0) {
        int nb = (int)((tail + 255) / 256);
        zero_tail_kernel<<<nb, 256>>>(out, main_elems, (long)out_size);
    }
}

// round 17
// speedup vs baseline: 1.0393x; 1.0159x over previous
#include <cuda_runtime.h>
#include <math.h>
#include <stdint.h>

// Problem constants
#define B_    4
#define T_    2048
#define DM_   2048
#define H_    16
#define HKV_  4
#define D_    128
#define M_    (B_*T_)      // 8192 tokens
#define NQ_   (H_*D_)      // 2048
#define NKV_  (HKV_*D_)    // 512

#define NSM_SLOTS 296      // 148 SMs x 2 CTAs (persistent Wo GEMM grid)

// Scratch (device globals: allocation-free per harness rules)
__device__ float g_q  [M_*NQ_];
__device__ float g_k  [M_*NKV_];
__device__ float g_v  [M_*NKV_];
__device__ float g_att[M_*NQ_];
__device__ float g_xr [M_*DM_];
__device__ float g_wq [NQ_*DM_];
__device__ float g_wk [NKV_*DM_];
__device__ float g_wv [NKV_*DM_];
__device__ float g_wo [DM_*NQ_];
__device__ float g_rope[T_*64*2];

// ---------------------------------------------------------------------------
// Helpers
// ---------------------------------------------------------------------------
__device__ __forceinline__ uint32_t smem_u32(const void* p) {
    uint32_t a;
    asm("{ .reg .u64 t; cvta.to.shared.u64 t, %1; cvt.u32.u64 %0, t; }" : "=r"(a) : "l"(p));
    return a;
}
__device__ __forceinline__ float rna_tf32(float v) {
    uint32_t b;
    asm("cvt.rna.tf32.f32 %0, %1;" : "=r"(b) : "f"(v));
    return __uint_as_float(b);
}
__device__ __forceinline__ uint32_t rna_tf32_u(float v) {
    uint32_t b;
    asm("cvt.rna.tf32.f32 %0, %1;" : "=r"(b) : "f"(v));
    return b;
}
__device__ __forceinline__ float ex2f(float v) {   // exp2, single MUFU op
    float r;
    asm("ex2.approx.f32 %0, %1;" : "=f"(r) : "f"(v));
    return r;
}

#define CP_ASYNC16(dst, src) \
    asm volatile("cp.async.cg.shared.global [%0], [%1], 16;" :: "r"(dst), "l"(src) : "memory")
#define CP_COMMIT()  asm volatile("cp.async.commit_group;" ::: "memory")
#define CP_WAIT(n)   asm volatile("cp.async.wait_group %0;" :: "n"(n) : "memory")

// mma.sync m16n8k8 tf32 (family-portable)
#define MMA_TF32(c, a, b) \
    asm volatile("mma.sync.aligned.m16n8k8.row.col.f32.tf32.tf32.f32 " \
        "{%0,%1,%2,%3}, {%4,%5,%6,%7}, {%8,%9}, {%0,%1,%2,%3};" \
        : "+f"((c)[0]), "+f"((c)[1]), "+f"((c)[2]), "+f"((c)[3]) \
        : "r"((a)[0]), "r"((a)[1]), "r"((a)[2]), "r"((a)[3]), \
          "r"((b)[0]), "r"((b)[1]))

// ---------------------------------------------------------------------------
// ONE fused prepass: RNA-round x/Wq/Wk/Wv/Wo + RoPE table, single launch.
// ---------------------------------------------------------------------------
__global__ void prepass_all_kernel(
    const float* __restrict__ x,  const float* __restrict__ Wq,
    const float* __restrict__ Wk, const float* __restrict__ Wv,
    const float* __restrict__ Wo,
    float* __restrict__ oxr, float* __restrict__ owq, float* __restrict__ owk,
    float* __restrict__ owv, float* __restrict__ owo, float* __restrict__ rope)
{
    const long n_x  = (long)M_  * DM_ / 4;
    const long n_q  = (long)NQ_ * DM_ / 4;
    const long n_kv = (long)NKV_* DM_ / 4;
    const long n_f4 = n_x + 2*n_q + 2*n_kv;
    long j = blockIdx.x * (long)blockDim.x + threadIdx.x;

    if (j < n_f4) {
        const float* src; float* dst; long i = j;
        if (i < n_x)                 { src = x;  dst = oxr; }
        else if ((i -= n_x) < n_q)   { src = Wq; dst = owq; }
        else if ((i -= n_q) < n_kv)  { src = Wk; dst = owk; }
        else if ((i -= n_kv) < n_kv) { src = Wv; dst = owv; }
        else                         { i -= n_kv; src = Wo; dst = owo; }
        float4 v = ((const float4*)src)[i];
        v.x = rna_tf32(v.x); v.y = rna_tf32(v.y); v.z = rna_tf32(v.z); v.w = rna_tf32(v.w);
        ((float4*)dst)[i] = v;
        return;
    }
    long r = j - n_f4;
    if (r < (long)T_ * 64) {
        int t = (int)(r >> 6), f = (int)(r & 63);
        double invf = exp(-((double)f / 64.0) * log(10000.0));
        float ang = (float)t * (float)invf;
        rope[r*2 + 0] = (float)cos((double)ang);
        rope[r*2 + 1] = (float)sin((double)ang);
    }
}

// ---------------------------------------------------------------------------
// GEMM core: CTA 128x128x32, 4 warps (64x64 warp tiles), 2 CTAs/SM. (proven)
// ---------------------------------------------------------------------------
#define STAGE_F 10240
#define STAGE_B (STAGE_F*4)

struct GemmCore {
    const float* Ab;
    const float* Wb;
    float* smf;
    uint32_t sbase;
    int tid, warp_m, warp_n, g, q4;

    __device__ __forceinline__ void load_stage(int s, int kt, int K) const {
        uint32_t aS = sbase + s * STAGE_B;
        uint32_t bS = aS + 20480;
        const float* ap = Ab + kt * 32;
        const float* wp = Wb + kt * 32;
        #pragma unroll
        for (int it = 0; it < 8; ++it) {
            int idx = it * 128 + tid;
            int row = idx >> 3, seg = idx & 7;
            uint32_t so = (uint32_t)row * 160 + (uint32_t)seg * 16;
            CP_ASYNC16(aS + so, ap + (size_t)row * K + seg * 4);
            CP_ASYNC16(bS + so, wp + (size_t)row * K + seg * 4);
        }
    }

    __device__ __forceinline__ void load_frags(const float* As_, const float* Bs_,
                                               int ks, uint32_t* a, uint32_t* b) const {
        const int col = ks * 8 + 2 * q4;
        #pragma unroll
        for (int ni = 0; ni < 8; ++ni) {
            float2 t = *(const float2*)&Bs_[(ni * 8 + g) * 40 + col];
            b[ni*2]   = __float_as_uint(t.x);
            b[ni*2+1] = __float_as_uint(t.y);
        }
        #pragma unroll
        for (int mi = 0; mi < 4; ++mi) {
            float2 t0 = *(const float2*)&As_[(mi * 16 + g) * 40 + col];
            float2 t1 = *(const float2*)&As_[(mi * 16 + g + 8) * 40 + col];
            a[mi*4+0] = __float_as_uint(t0.x);
            a[mi*4+2] = __float_as_uint(t0.y);
            a[mi*4+1] = __float_as_uint(t1.x);
            a[mi*4+3] = __float_as_uint(t1.y);
        }
    }

    __device__ __forceinline__ void mainloop(float acc[4][8][4], int K) const {
        const int KT = K >> 5;
        load_stage(0, 0, K);
        CP_COMMIT();
        for (int kt = 0; kt < KT; ++kt) {
            const int cur = kt & 1;
            CP_WAIT(0);
            __syncthreads();
            if (kt + 1 < KT) {
                load_stage(cur ^ 1, kt + 1, K);
                CP_COMMIT();
            }
            const float* As_ = smf + cur * STAGE_F + warp_m * (64 * 40);
            const float* Bs_ = smf + cur * STAGE_F + 5120 + warp_n * (64 * 40);

            uint32_t aF[2][16], bF[2][16];
            load_frags(As_, Bs_, 0, aF[0], bF[0]);
            #pragma unroll
            for (int ks = 0; ks < 4; ++ks) {
                const int cb = ks & 1;
                if (ks < 3) load_frags(As_, Bs_, ks + 1, aF[cb ^ 1], bF[cb ^ 1]);
                #pragma unroll
                for (int mi = 0; mi < 4; ++mi)
                    #pragma unroll
                    for (int ni = 0; ni < 8; ++ni)
                        MMA_TF32(acc[mi][ni], &aF[cb][mi*4], &bF[cb][ni*2]);
            }
        }
        __syncthreads();
    }

    __device__ __forceinline__ void epilogue_plain(float acc[4][8][4], float* C,
                                                   int N, int row0, int col0, bool rnd) const {
        #pragma unroll
        for (int mi = 0; mi < 4; ++mi) {
            const int r = row0 + warp_m * 64 + mi * 16 + g;
            #pragma unroll
            for (int ni = 0; ni < 8; ++ni) {
                const int c = col0 + warp_n * 64 + ni * 8 + q4 * 2;
                float e0 = acc[mi][ni][0], e1 = acc[mi][ni][1];
                float e2 = acc[mi][ni][2], e3 = acc[mi][ni][3];
                if (rnd) { e0 = rna_tf32(e0); e1 = rna_tf32(e1); e2 = rna_tf32(e2); e3 = rna_tf32(e3); }
                *(float2*)&C[(size_t)r * N + c]       = make_float2(e0, e1);
                *(float2*)&C[(size_t)(r + 8) * N + c] = make_float2(e2, e3);
            }
        }
    }

    __device__ __forceinline__ void epilogue_fuse(float acc[4][8][4], float* C,
                                                  int N, int row0, int col0,
                                                  const float* rope, bool rnd) const {
        float* Cs = smf;
        #pragma unroll
        for (int mi = 0; mi < 4; ++mi) {
            const int r = warp_m * 64 + mi * 16 + g;
            #pragma unroll
            for (int ni = 0; ni < 8; ++ni) {
                const int c = warp_n * 64 + ni * 8 + q4 * 2;
                Cs[r * 129 + c]           = acc[mi][ni][0];
                Cs[r * 129 + c + 1]       = acc[mi][ni][1];
                Cs[(r + 8) * 129 + c]     = acc[mi][ni][2];
                Cs[(r + 8) * 129 + c + 1] = acc[mi][ni][3];
            }
        }
        __syncthreads();
        {
            const int row = row0 + tid;
            const float* cr = Cs + tid * 129;
            float ss = 0.f;
            #pragma unroll 16
            for (int j = 0; j < 128; ++j) ss += cr[j] * cr[j];
            const float sc = rsqrtf(ss * (1.0f/128.0f) + 1.1920928955078125e-07f);
            const float* rp = rope + (row & (T_ - 1)) * 128;
            float* op = C + (size_t)row * N + col0;
            #pragma unroll
            for (int f4 = 0; f4 < 64; f4 += 4) {
                float4 o1, o2;
                #pragma unroll
                for (int e = 0; e < 4; ++e) {
                    const int f = f4 + e;
                    const float v1 = cr[f] * sc;
                    const float v2 = cr[f + 64] * sc;
                    const float cz = rp[2*f], sz = rp[2*f + 1];
                    float r1 =  v1 * cz + v2 * sz;
                    float r2 = -v1 * sz + v2 * cz;
                    if (rnd) { r1 = rna_tf32(r1); r2 = rna_tf32(r2); }
                    (&o1.x)[e] = r1;
                    (&o2.x)[e] = r2;
                }
                *(float4*)(op + f4)      = o1;
                *(float4*)(op + f4 + 64) = o2;
            }
        }
        __syncthreads();
    }
};

// ---------------------------------------------------------------------------
// GRIDDED merged q/k/v GEMM (proven R16 config).
// ---------------------------------------------------------------------------
__global__ __launch_bounds__(128, 2)
void tc_gemm_qkv(const float* __restrict__ A,
                 const float* __restrict__ Wq, const float* __restrict__ Wk,
                 const float* __restrict__ Wv,
                 float* __restrict__ Cq, float* __restrict__ Ck, float* __restrict__ Cv,
                 const float* __restrict__ rope)
{
    extern __shared__ float smf[];
    const int bxg = blockIdx.x, by = blockIdx.y;

    const float* Wbase; float* Cout; int N, bxl; bool fuse, rnd;
    if (bxg < 16)      { Wbase = Wq; Cout = Cq; N = NQ_;  bxl = bxg;      fuse = true;  rnd = false; }
    else if (bxg < 20) { Wbase = Wk; Cout = Ck; N = NKV_; bxl = bxg - 16; fuse = true;  rnd = true;  }
    else               { Wbase = Wv; Cout = Cv; N = NKV_; bxl = bxg - 20; fuse = false; rnd = true;  }

    GemmCore core;
    core.smf = smf; core.sbase = smem_u32(smf);
    core.tid = threadIdx.x;
    const int lane = core.tid & 31;
    const int wid  = core.tid >> 5;
    core.warp_m = wid >> 1; core.warp_n = wid & 1;
    core.g = lane >> 2; core.q4 = lane & 3;
    core.Ab = A + (size_t)(by * 128) * DM_;
    core.Wb = Wbase + (size_t)(bxl * 128) * DM_;

    float acc[4][8][4];
    #pragma unroll
    for (int mi = 0; mi < 4; ++mi)
        #pragma unroll
        for (int ni = 0; ni < 8; ++ni)
            #pragma unroll
            for (int e = 0; e < 4; ++e) acc[mi][ni][e] = 0.f;

    core.mainloop(acc, DM_);

    if (fuse) core.epilogue_fuse (acc, Cout, N, by * 128, bxl * 128, rope, rnd);
    else      core.epilogue_plain(acc, Cout, N, by * 128, bxl * 128, rnd);
}

// PERSISTENT Wo projection GEMM (proven; 407 us, tensor 64%).
__global__ __launch_bounds__(128, 2)
void tc_gemm_wo(const float* __restrict__ A, const float* __restrict__ W,
                float* __restrict__ C)
{
    extern __shared__ float smf[];

    GemmCore core;
    core.smf = smf; core.sbase = smem_u32(smf);
    core.tid = threadIdx.x;
    const int lane = core.tid & 31;
    const int wid  = core.tid >> 5;
    core.warp_m = wid >> 1; core.warp_n = wid & 1;
    core.g = lane >> 2; core.q4 = lane & 3;

    const int NT = (NQ_/128) * (M_/128);
    for (int tile = blockIdx.x; tile < NT; tile += NSM_SLOTS) {
        const int bx = tile % (NQ_/128);
        const int by = tile / (NQ_/128);

        core.Ab = A + (size_t)(by * 128) * DM_;
        core.Wb = W + (size_t)(bx * 128) * DM_;

        float acc[4][8][4];
        #pragma unroll
        for (int mi = 0; mi < 4; ++mi)
            #pragma unroll
            for (int ni = 0; ni < 8; ++ni)
                #pragma unroll
                for (int e = 0; e < 4; ++e) acc[mi][ni][e] = 0.f;

        core.mainloop(acc, DM_);
        core.epilogue_plain(acc, C, NQ_, by * 128, bx * 128, false);
    }
}

// ---------------------------------------------------------------------------
// Tensor-core flash attention, 2 CTAs/SM version.
// BM=64 (4 warps, 128 threads), BN=64, single-buffered K/V (the co-resident
// CTA covers load latency). Smem 87 KB: P[64x68] | K[64x136] | V[64x136].
// V load overlaps S+softmax via split commit groups. exp2 domain, conditional
// O-rescale (from R16). Q staged through the K+V region.
// ---------------------------------------------------------------------------
#define FP_F 4352              // P floats (64*68)
#define FKV 8704               // K/V buffer floats (64*136)

__global__ __launch_bounds__(128, 2)
void flash_tc(const float* __restrict__ Q, const float* __restrict__ K,
              const float* __restrict__ V, float* __restrict__ Out)
{
    extern __shared__ float sm[];
    float* Psm = sm;                 // 64 x 68
    float* Ks  = sm + FP_F;          // 64 x 136
    float* Vs  = sm + FP_F + FKV;    // 64 x 136
    const uint32_t sb = smem_u32(sm);
    const uint32_t kaddr = sb + FP_F*4;
    const uint32_t vaddr = sb + (FP_F + FKV)*4;

    const int qt  = (int)gridDim.x - 1 - (int)blockIdx.x;   // big tiles first
    const int h   = blockIdx.y;
    const int b   = blockIdx.z;
    const int kvh = h >> 2;
    const int tid = threadIdx.x;
    const int lane = tid & 31;
    const int wm   = tid >> 5;       // 0..3
    const int g    = lane >> 2;
    const int q4   = lane & 3;

    // 1/sqrt(128) * log2(e)
    const float scale2 = 0.08838834764831843f * 1.4426950408889634f;

    {   // stage Q tile (64 x 128) into K region, stride 136
        const float* qp = Q + (size_t)(b*T_ + qt*64) * NQ_ + h*128;
        #pragma unroll
        for (int it = 0; it < 16; ++it) {
            int idx = it * 128 + tid;
            int row = idx >> 5, seg = idx & 31;
            CP_ASYNC16(kaddr + ((uint32_t)row*136 + seg*4)*4, qp + (size_t)row*NQ_ + seg*4);
        }
        CP_COMMIT();
        CP_WAIT(0);
        __syncthreads();
    }

    uint32_t qf[16][4];
    {
        const float* qs = Ks + (wm*16 + g)*136 + 2*q4;
        #pragma unroll
        for (int ks = 0; ks < 16; ++ks) {
            float2 t0 = *(const float2*)(qs + ks*8);
            float2 t1 = *(const float2*)(qs + ks*8 + 8*136);
            qf[ks][0] = rna_tf32_u(t0.x * scale2);
            qf[ks][2] = rna_tf32_u(t0.y * scale2);
            qf[ks][1] = rna_tf32_u(t1.x * scale2);
            qf[ks][3] = rna_tf32_u(t1.y * scale2);
        }
    }

    const int njt = qt + 1;

    auto load_k = [&](int jt) {
        const float* kp = K + (size_t)(b*T_ + jt*64) * NKV_ + kvh*128;
        #pragma unroll
        for (int it = 0; it < 16; ++it) {
            int idx = it * 128 + tid;
            int row = idx >> 5, seg = idx & 31;
            CP_ASYNC16(kaddr + ((uint32_t)row*136 + seg*4)*4, kp + (size_t)row*NKV_ + seg*4);
        }
    };
    auto load_v = [&](int jt) {
        const float* vp = V + (size_t)(b*T_ + jt*64) * NKV_ + kvh*128;
        #pragma unroll
        for (int it = 0; it < 16; ++it) {
            int idx = it * 128 + tid;
            int row = idx >> 5, seg = idx & 31;
            CP_ASYNC16(vaddr + ((uint32_t)row*136 + seg*4)*4, vp + (size_t)row*NKV_ + seg*4);
        }
    };

    float m0 = -1e30f, m1 = -1e30f, l0 = 0.f, l1 = 0.f;
    float O[16][4];
    #pragma unroll
    for (int nf = 0; nf < 16; ++nf)
        #pragma unroll
        for (int e = 0; e < 4; ++e) O[nf][e] = 0.f;

    const int row_g0 = qt*64 + wm*16 + g;
    float* Prow = Psm + (wm*16 + g)*68;

    for (int jt = 0; jt < njt; ++jt) {
        __syncthreads();   // (A) all warps done with prior K/V/Q-stage
        load_k(jt); CP_COMMIT();
        load_v(jt); CP_COMMIT();
        CP_WAIT(1);        // K resident
        __syncthreads();   // (B) K visible to all warps

        float S[8][4];
        #pragma unroll
        for (int nf = 0; nf < 8; ++nf)
            #pragma unroll
            for (int e = 0; e < 4; ++e) S[nf][e] = 0.f;

        #pragma unroll
        for (int ks = 0; ks < 16; ++ks) {
            const float* kb = Ks + g*136 + ks*8 + 2*q4;
            #pragma unroll
            for (int nf = 0; nf < 8; ++nf) {
                float2 t = *(const float2*)(kb + nf*8*136);
                uint32_t bb[2] = { __float_as_uint(t.x), __float_as_uint(t.y) };
                MMA_TF32(S[nf], qf[ks], bb);
            }
        }

        if (jt == qt) {    // diagonal tile: causal mask
            const int colb = jt*64 + 2*q4;
            #pragma unroll
            for (int nf = 0; nf < 8; ++nf) {
                const int c0 = colb + nf*8;
                if (c0     > row_g0)     S[nf][0] = -1e30f;
                if (c0 + 1 > row_g0)     S[nf][1] = -1e30f;
                if (c0     > row_g0 + 8) S[nf][2] = -1e30f;
                if (c0 + 1 > row_g0 + 8) S[nf][3] = -1e30f;
            }
        }

        float rm0 = -1e30f, rm1 = -1e30f;
        #pragma unroll
        for (int nf = 0; nf < 8; ++nf) {
            rm0 = fmaxf(rm0, fmaxf(S[nf][0], S[nf][1]));
            rm1 = fmaxf(rm1, fmaxf(S[nf][2], S[nf][3]));
        }
        rm0 = fmaxf(rm0, __shfl_xor_sync(0xffffffffu, rm0, 1));
        rm0 = fmaxf(rm0, __shfl_xor_sync(0xffffffffu, rm0, 2));
        rm1 = fmaxf(rm1, __shfl_xor_sync(0xffffffffu, rm1, 1));
        rm1 = fmaxf(rm1, __shfl_xor_sync(0xffffffffu, rm1, 2));

        const float mn0 = fmaxf(m0, rm0), mn1 = fmaxf(m1, rm1);
        const bool chg = __any_sync(0xffffffffu, (mn0 > m0) | (mn1 > m1));

        float rs0 = 0.f, rs1 = 0.f;
        #pragma unroll
        for (int nf = 0; nf < 8; ++nf) {
            S[nf][0] = ex2f(S[nf][0] - mn0);
            S[nf][1] = ex2f(S[nf][1] - mn0);
            S[nf][2] = ex2f(S[nf][2] - mn1);
            S[nf][3] = ex2f(S[nf][3] - mn1);
            rs0 += S[nf][0] + S[nf][1];
            rs1 += S[nf][2] + S[nf][3];
        }
        rs0 += __shfl_xor_sync(0xffffffffu, rs0, 1);
        rs0 += __shfl_xor_sync(0xffffffffu, rs0, 2);
        rs1 += __shfl_xor_sync(0xffffffffu, rs1, 1);
        rs1 += __shfl_xor_sync(0xffffffffu, rs1, 2);

        if (chg) {
            const float corr0 = ex2f(m0 - mn0);
            const float corr1 = ex2f(m1 - mn1);
            l0 = l0*corr0 + rs0;
            l1 = l1*corr1 + rs1;
            #pragma unroll
            for (int nf = 0; nf < 16; ++nf) {
                O[nf][0] *= corr0; O[nf][1] *= corr0;
                O[nf][2] *= corr1; O[nf][3] *= corr1;
            }
        } else {
            l0 += rs0;
            l1 += rs1;
        }
        m0 = mn0; m1 = mn1;

        // P write/read is intra-warp (each warp owns its 16 P rows)
        #pragma unroll
        for (int nf = 0; nf < 8; ++nf) {
            const int c = nf*8 + 2*q4;
            *(float2*)(Prow + c)        = make_float2(rna_tf32(S[nf][0]), rna_tf32(S[nf][1]));
            *(float2*)(Prow + 8*68 + c) = make_float2(rna_tf32(S[nf][2]), rna_tf32(S[nf][3]));
        }
        __syncwarp();

        CP_WAIT(0);        // V resident (load overlapped S+softmax)
        __syncthreads();   // (C) V visible to all warps

        #pragma unroll
        for (int ks = 0; ks < 8; ++ks) {
            uint32_t a[4];
            a[0] = __float_as_uint(Prow[ks*8 + q4]);
            a[2] = __float_as_uint(Prow[ks*8 + q4 + 4]);
            a[1] = __float_as_uint(Prow[8*68 + ks*8 + q4]);
            a[3] = __float_as_uint(Prow[8*68 + ks*8 + q4 + 4]);
            const float* vb = Vs + (ks*8 + q4)*136 + g;
            #pragma unroll
            for (int nf = 0; nf < 16; ++nf) {
                uint32_t bb[2] = { __float_as_uint(vb[nf*8]),
                                   __float_as_uint(vb[nf*8 + 4*136]) };
                MMA_TF32(O[nf], a, bb);
            }
        }
    }

    const float inv0 = 1.0f / l0;
    const float inv1 = 1.0f / l1;
    float* o0 = Out + (size_t)(b*T_ + row_g0)     * NQ_ + h*128 + 2*q4;
    float* o1 = Out + (size_t)(b*T_ + row_g0 + 8) * NQ_ + h*128 + 2*q4;
    #pragma unroll
    for (int nf = 0; nf < 16; ++nf) {
        *(float2*)(o0 + nf*8) = make_float2(rna_tf32(O[nf][0]*inv0), rna_tf32(O[nf][1]*inv0));
        *(float2*)(o1 + nf*8) = make_float2(rna_tf32(O[nf][2]*inv1), rna_tf32(O[nf][3]*inv1));
    }
}

// ---------------------------------------------------------------------------
__global__ void zero_tail_kernel(float* __restrict__ out, long start, long total) {
    long idx = start + blockIdx.x * (long)blockDim.x + threadIdx.x;
    if (idx < total) out[idx] = 0.f;
}

// ---------------------------------------------------------------------------
extern "C" void kernel_launch(void* const* d_in, const int* in_sizes, int n_in,
                              void* d_out, int out_size) {
    const float* x  = (const float*)d_in[0];
    const float* Wq = (const float*)d_in[1];
    const float* Wk = (const float*)d_in[2];
    const float* Wv = (const float*)d_in[3];
    const float* Wo = (const float*)d_in[4];
    float* out = (float*)d_out;

    float *q, *k, *v, *att, *xr, *wq, *wk, *wv, *wo, *rope;
    cudaGetSymbolAddress((void**)&q,    g_q);
    cudaGetSymbolAddress((void**)&k,    g_k);
    cudaGetSymbolAddress((void**)&v,    g_v);
    cudaGetSymbolAddress((void**)&att,  g_att);
    cudaGetSymbolAddress((void**)&xr,   g_xr);
    cudaGetSymbolAddress((void**)&wq,   g_wq);
    cudaGetSymbolAddress((void**)&wk,   g_wk);
    cudaGetSymbolAddress((void**)&wv,   g_wv);
    cudaGetSymbolAddress((void**)&wo,   g_wo);
    cudaGetSymbolAddress((void**)&rope, g_rope);

    // Launches: 1 prepass, 2 qkv GEMM, 3 flash (2 CTA/SM), 4 Wo GEMM, 5 tail.
    const long n_f4 = ((long)M_*DM_ + 2L*NQ_*DM_ + 2L*NKV_*DM_) / 4;
    const long total_thr = n_f4 + (long)T_*64;
    prepass_all_kernel<<<(int)((total_thr + 255)/256), 256>>>(
        x, Wq, Wk, Wv, Wo, xr, wq, wk, wv, wo, rope);

    const int gsm = 2 * STAGE_B;   // 81920 B -> two CTAs per SM
    cudaFuncSetAttribute(tc_gemm_qkv, cudaFuncAttributeMaxDynamicSharedMemorySize, gsm);
    cudaFuncSetAttribute(tc_gemm_wo,  cudaFuncAttributeMaxDynamicSharedMemorySize, gsm);

    tc_gemm_qkv<<<dim3(24, M_/128), dim3(128), gsm>>>(xr, wq, wk, wv, q, k, v, rope);

    const int fsm = (FP_F + 2*FKV) * 4;   // 87040 B -> two CTAs per SM
    cudaFuncSetAttribute(flash_tc, cudaFuncAttributeMaxDynamicSharedMemorySize, fsm);
    flash_tc<<<dim3(T_/64, H_, B_), dim3(128), fsm>>>(q, k, v, att);

    tc_gemm_wo<<<NSM_SLOTS, dim3(128), gsm>>>(att, wo, out);

    long main_elems = (long)M_ * NQ_;
    long tail = (long)out_size - main_elems;
    if (tail > 0) {
        int nb = (int)((tail + 255) / 256);
        zero_tail_kernel<<<nb, 256>>>(out, main_elems, (long)out_size);
    }
}